// round 1
// baseline (speedup 1.0000x reference)
#include <cuda_runtime.h>
#include <math.h>

#define N_SPK 1024
#define M_UTT 32
#define D_DIM 512
#define R_ROWS (N_SPK * M_UTT)   // 32768 rows of E
#define EPS 1e-6f

// ---- scratch (no allocations allowed; __device__ globals are the sanctioned path) ----
__device__ float g_centroid[N_SPK * D_DIM];  // (1024, 512) fp32 centroids
__device__ float g_csq[N_SPK];               // |c_k|^2
__device__ float g_cinv[N_SPK];              // 1/|c_k|
__device__ float g_esq[R_ROWS];              // |e_r|^2
__device__ float g_einv[R_ROWS];             // 1/|e_r|
__device__ float g_Z[R_ROWS];                // softmax denominators (accumulated)
__device__ float g_own[R_ROWS];              // own-speaker (LOO) logit per row

// ---------------------------------------------------------------------------
// Kernel 1: centroids + |c|^2 + 1/|c|. One block per speaker, 512 threads (one per d).
// ---------------------------------------------------------------------------
__global__ void centroid_kernel(const float* __restrict__ dvecs) {
    int j = blockIdx.x;
    int d = threadIdx.x;
    const float* base = dvecs + (size_t)j * M_UTT * D_DIM + d;
    float s = 0.f;
#pragma unroll
    for (int m = 0; m < M_UTT; m++) s += base[m * D_DIM];
    float c = s * (1.0f / M_UTT);
    g_centroid[j * D_DIM + d] = c;

    __shared__ float sh[512];
    sh[d] = c * c;
    __syncthreads();
    for (int off = 256; off > 0; off >>= 1) {
        if (d < off) sh[d] += sh[d + off];
        __syncthreads();
    }
    if (d == 0) {
        float cs = sh[0];
        g_csq[j]  = cs;
        g_cinv[j] = rsqrtf(cs);
    }
}

// ---------------------------------------------------------------------------
// Kernel 2: per-row |e|^2 and 1/|e|. One warp per row.
// ---------------------------------------------------------------------------
__global__ void enorm_kernel(const float* __restrict__ dvecs) {
    int warp = (blockIdx.x * blockDim.x + threadIdx.x) >> 5;
    int lane = threadIdx.x & 31;
    if (warp >= R_ROWS) return;
    const float* row = dvecs + (size_t)warp * D_DIM;
    float s = 0.f;
#pragma unroll
    for (int d = lane; d < D_DIM; d += 32) {
        float v = row[d];
        s += v * v;
    }
#pragma unroll
    for (int off = 16; off > 0; off >>= 1) s += __shfl_xor_sync(0xffffffffu, s, off);
    if (lane == 0) {
        g_esq[warp]  = s;
        g_einv[warp] = rsqrtf(s);
    }
}

// ---------------------------------------------------------------------------
// Kernel 3: zero the Z accumulators (graph runs repeatedly; must re-zero each launch).
// ---------------------------------------------------------------------------
__global__ void zinit_kernel() {
    int i = blockIdx.x * blockDim.x + threadIdx.x;
    if (i < R_ROWS) g_Z[i] = 0.f;
}

// ---------------------------------------------------------------------------
// Kernel 4: fused SGEMM (E @ C^T) + epilogue.
//   BM=128 rows, BN=128 centroid-cols, BK=8, 256 threads, 8x8 microtile.
//   Epilogue: cos -> clamp -> *w+b -> exp, row partial sums -> atomicAdd(g_Z),
//   own-speaker element replaced with leave-one-out cosine (derived algebraically).
// ---------------------------------------------------------------------------
#define BM 128
#define BN 128
#define BK 8
#define TM 8
#define TN 8

__global__ __launch_bounds__(256) void gemm_loss_kernel(
    const float* __restrict__ A,      // dvecs as (32768, 512) row-major
    const float* __restrict__ wp,
    const float* __restrict__ bp)
{
    __shared__ float As[BK][BM];
    __shared__ float Bs[BK][BN];
    __shared__ float zsh[BM];

    const int tid = threadIdx.x;
    const int tx  = tid % 16;       // column group
    const int ty  = tid / 16;       // row group
    const int row0 = blockIdx.y * BM;
    const int col0 = blockIdx.x * BN;

    float acc[TM][TN];
#pragma unroll
    for (int i = 0; i < TM; i++)
#pragma unroll
        for (int j = 0; j < TN; j++) acc[i][j] = 0.f;

    // load assignment: each thread loads one float4 of A and one of B per stage
    const int lr  = tid >> 1;          // 0..127: tile row / tile col
    const int lk4 = (tid & 1) * 4;     // 0 or 4: k offset

    const float* aBase = A + (size_t)(row0 + lr) * D_DIM + lk4;
    const float* bBase = g_centroid + (size_t)(col0 + lr) * D_DIM + lk4;

    for (int kt = 0; kt < D_DIM; kt += BK) {
        float4 av = *reinterpret_cast<const float4*>(aBase + kt);
        float4 bv = *reinterpret_cast<const float4*>(bBase + kt);
        As[lk4 + 0][lr] = av.x; As[lk4 + 1][lr] = av.y;
        As[lk4 + 2][lr] = av.z; As[lk4 + 3][lr] = av.w;
        Bs[lk4 + 0][lr] = bv.x; Bs[lk4 + 1][lr] = bv.y;
        Bs[lk4 + 2][lr] = bv.z; Bs[lk4 + 3][lr] = bv.w;
        __syncthreads();

#pragma unroll
        for (int k = 0; k < BK; k++) {
            float a[TM], b[TN];
#pragma unroll
            for (int i = 0; i < TM; i++) a[i] = As[k][ty * TM + i];
#pragma unroll
            for (int j = 0; j < TN; j++) b[j] = Bs[k][tx * TN + j];
#pragma unroll
            for (int i = 0; i < TM; i++)
#pragma unroll
                for (int j = 0; j < TN; j++) acc[i][j] = fmaf(a[i], b[j], acc[i][j]);
        }
        __syncthreads();
    }

    // ----- epilogue -----
    const float w  = *wp;
    const float bb = *bp;

    if (tid < BM) zsh[tid] = 0.f;
    __syncthreads();

    // cache per-thread column constants
    float cinv[TN], csq[TN];
#pragma unroll
    for (int j = 0; j < TN; j++) {
        int c = col0 + tx * TN + j;
        cinv[j] = g_cinv[c];
        csq[j]  = g_csq[c];
    }

    const float inv_m1  = 1.0f / (float)(M_UTT - 1);
    const float inv_m1s = inv_m1 * inv_m1;

#pragma unroll
    for (int i = 0; i < TM; i++) {
        int r = row0 + ty * TM + i;
        float einv = g_einv[r];
        float esq  = g_esq[r];
        int jown   = r >> 5;           // r / M_UTT
        float rowsum = 0.f;
#pragma unroll
        for (int j = 0; j < TN; j++) {
            int c = col0 + tx * TN + j;
            float dot = acc[i][j];
            float cosv;
            if (c == jown) {
                // leave-one-out replacement
                float dot_loo = ((float)M_UTT * dot - esq) * inv_m1;
                float closq   = ((float)(M_UTT * M_UTT) * csq[j]
                                 - 2.0f * (float)M_UTT * dot + esq) * inv_m1s;
                cosv = dot_loo * einv * rsqrtf(closq);
                float logit = fmaxf(cosv, EPS) * w + bb;
                g_own[r] = logit;
                rowsum += __expf(logit);
            } else {
                cosv = dot * einv * cinv[j];
                float logit = fmaxf(cosv, EPS) * w + bb;
                rowsum += __expf(logit);
            }
        }
        atomicAdd(&zsh[ty * TM + i], rowsum);
    }
    __syncthreads();
    if (tid < BM) atomicAdd(&g_Z[row0 + tid], zsh[tid]);
}

// ---------------------------------------------------------------------------
// Kernel 5: final loss reduction. L = sum_r ( log(Z[r]) - own_logit[r] ).
// ---------------------------------------------------------------------------
__global__ void loss_kernel(float* __restrict__ out) {
    const int tid = threadIdx.x;
    float s = 0.f;
    for (int r = tid; r < R_ROWS; r += blockDim.x)
        s += logf(g_Z[r]) - g_own[r];

    __shared__ float sh[1024];
    sh[tid] = s;
    __syncthreads();
    for (int off = 512; off > 0; off >>= 1) {
        if (tid < off) sh[tid] += sh[tid + off];
        __syncthreads();
    }
    if (tid == 0) out[0] = sh[0];
}

// ---------------------------------------------------------------------------
extern "C" void kernel_launch(void* const* d_in, const int* in_sizes, int n_in,
                              void* d_out, int out_size) {
    const float* dvecs = (const float*)d_in[0];
    const float* w     = (const float*)d_in[1];
    const float* b     = (const float*)d_in[2];
    float* out         = (float*)d_out;

    centroid_kernel<<<N_SPK, 512>>>(dvecs);
    enorm_kernel<<<R_ROWS / 8, 256>>>(dvecs);        // 8 warps/block, 1 row/warp
    zinit_kernel<<<(R_ROWS + 255) / 256, 256>>>();
    gemm_loss_kernel<<<dim3(N_SPK / BN, R_ROWS / BM), 256>>>(dvecs, w, b);
    loss_kernel<<<1, 1024>>>(out);
}

// round 3
// speedup vs baseline: 6.0260x; 6.0260x over previous
#include <cuda_runtime.h>
#include <cuda_bf16.h>
#include <math.h>
#include <stdint.h>

#define N_SPK 1024
#define M_UTT 32
#define D_DIM 512
#define R_ROWS (N_SPK * M_UTT)
#define EPS 1e-6f

// ---------------- device scratch (no allocations allowed) ----------------
__device__ __nv_bfloat16 g_Abf[R_ROWS * D_DIM];   // 32 MB  bf16 dvecs
__device__ __nv_bfloat16 g_Cbf[N_SPK * D_DIM];    // 1 MB   bf16 centroids
__device__ float g_csq[N_SPK];
__device__ float g_cinv[N_SPK];
__device__ float g_esq[R_ROWS];
__device__ float g_einv[R_ROWS];
__device__ float g_Zp[8 * R_ROWS];                // per-col-tile softmax partials
__device__ float g_own[R_ROWS];                   // own-speaker (LOO) logit

// ---------------- PTX helpers ----------------
__device__ __forceinline__ uint32_t smem_u32(const void* p) {
    uint32_t a;
    asm("{ .reg .u64 t; cvta.to.shared.u64 t, %1; cvt.u32.u64 %0, t; }" : "=r"(a) : "l"(p));
    return a;
}
__device__ __forceinline__ void cp_async16(uint32_t dst, const void* src) {
    asm volatile("cp.async.cg.shared.global.L2::128B [%0], [%1], 16;\n" :: "r"(dst), "l"(src));
}
__device__ __forceinline__ void cp_commit() {
    asm volatile("cp.async.commit_group;\n" ::: "memory");
}
template <int N>
__device__ __forceinline__ void cp_wait() {
    asm volatile("cp.async.wait_group %0;\n" :: "n"(N) : "memory");
}
__device__ __forceinline__ void ldmx4(uint32_t* r, uint32_t addr) {
    asm volatile("ldmatrix.sync.aligned.m8n8.x4.shared.b16 {%0,%1,%2,%3}, [%4];"
                 : "=r"(r[0]), "=r"(r[1]), "=r"(r[2]), "=r"(r[3]) : "r"(addr));
}
__device__ __forceinline__ void mma16816(float* c, const uint32_t* a, uint32_t b0, uint32_t b1) {
    asm volatile(
        "mma.sync.aligned.m16n8k16.row.col.f32.bf16.bf16.f32 "
        "{%0,%1,%2,%3}, {%4,%5,%6,%7}, {%8,%9}, {%0,%1,%2,%3};"
        : "+f"(c[0]), "+f"(c[1]), "+f"(c[2]), "+f"(c[3])
        : "r"(a[0]), "r"(a[1]), "r"(a[2]), "r"(a[3]), "r"(b0), "r"(b1));
}
__device__ __forceinline__ uint32_t swz(uint32_t bo) {   // SW128: bits[4:6] ^= bits[7:9]
    return bo ^ ((bo >> 3) & 0x70);
}

// fast exp on the FMA pipe (no MUFU): valid for |x| <= ~80, here x in [-5, 5]
__device__ __forceinline__ float exp_fast(float x) {
    const float LOG2E = 1.4426950408889634f;
    float y = x * LOG2E;
    float z = y + 12582912.0f;                 // round-to-nearest via magic constant
    float f = y - (z - 12582912.0f);           // f in [-0.5, 0.5]
    int   n = __float_as_int(z) - 0x4B400000;  // integer part
    // 2^f, degree-5 Taylor in ln2 (rel err ~2.4e-6 at |f|=0.5)
    float p = 0.001333355814642844f;
    p = fmaf(p, f, 0.009618129107628477f);
    p = fmaf(p, f, 0.055504108664821580f);
    p = fmaf(p, f, 0.240226506959100700f);
    p = fmaf(p, f, 0.693147180559945300f);
    p = fmaf(p, f, 1.0f);
    float s = __int_as_float((n + 127) << 23);
    return p * s;
}

// ---------------------------------------------------------------------------
// Kernel 1: fp32->bf16 convert + |e|^2, 1/|e|.  One warp per row.
// ---------------------------------------------------------------------------
__global__ void conv_kernel(const float* __restrict__ dvecs) {
    int row  = (blockIdx.x * blockDim.x + threadIdx.x) >> 5;
    int lane = threadIdx.x & 31;
    const float2* src = (const float2*)(dvecs + (size_t)row * D_DIM);
    __nv_bfloat162* dst = (__nv_bfloat162*)(g_Abf + (size_t)row * D_DIM);
    float s = 0.f;
#pragma unroll
    for (int k = 0; k < 8; k++) {
        float2 v = src[lane + k * 32];
        s += v.x * v.x + v.y * v.y;
        dst[lane + k * 32] = __floats2bfloat162_rn(v.x, v.y);
    }
#pragma unroll
    for (int off = 16; off > 0; off >>= 1) s += __shfl_xor_sync(0xffffffffu, s, off);
    if (lane == 0) {
        g_esq[row]  = s;
        g_einv[row] = rsqrtf(s);
    }
}

// ---------------------------------------------------------------------------
// Kernel 2: centroids (bf16) + |c|^2, 1/|c|.  One block per speaker.
// ---------------------------------------------------------------------------
__global__ void centroid_kernel(const float* __restrict__ dvecs) {
    int j = blockIdx.x;
    int d = threadIdx.x;
    const float* base = dvecs + (size_t)j * M_UTT * D_DIM + d;
    float s = 0.f;
#pragma unroll
    for (int m = 0; m < M_UTT; m++) s += base[m * D_DIM];
    float c = s * (1.0f / M_UTT);
    g_Cbf[j * D_DIM + d] = __float2bfloat16(c);

    __shared__ float sh[512];
    sh[d] = c * c;
    __syncthreads();
    for (int off = 256; off > 0; off >>= 1) {
        if (d < off) sh[d] += sh[d + off];
        __syncthreads();
    }
    if (d == 0) {
        g_csq[j]  = sh[0];
        g_cinv[j] = rsqrtf(sh[0]);
    }
}

// ---------------------------------------------------------------------------
// Kernel 3: bf16 mma.sync GEMM (BM=128, BN=128, BK=64, 3-stage cp.async)
// + fused softmax epilogue.  Grid: (8 col tiles, 256 row tiles), 256 threads.
// ---------------------------------------------------------------------------
#define BK 64
#define STAGES 3
#define A_BYTES 16384                  // 128 x 128B
#define B_BYTES 16384
#define STAGE_BYTES (A_BYTES + B_BYTES)
#define OFF_EINV  0
#define OFF_ESQ   512
#define OFF_CINV  1024
#define OFF_CSQ   1536
#define OFF_PART  2048                 // 4 x 128 floats
#define OFF_STAGE 4096
#define SMEM_TOTAL (OFF_STAGE + STAGES * STAGE_BYTES)   // 102400

__global__ void __launch_bounds__(256, 2)
gemm_loss_kernel(const float* __restrict__ wp, const float* __restrict__ bp) {
    extern __shared__ char smem[];
    const uint32_t sb = smem_u32(smem);
    const int tid  = threadIdx.x;
    const int wid  = tid >> 5;
    const int lane = tid & 31;
    const int wy   = wid >> 2;          // 0..1  (64-row slice)
    const int wx   = wid & 3;           // 0..3  (32-col slice)
    const int col0 = blockIdx.x * 128;
    const int row0 = blockIdx.y * 128;

    float* sh_einv = (float*)(smem + OFF_EINV);
    float* sh_esq  = (float*)(smem + OFF_ESQ);
    float* sh_cinv = (float*)(smem + OFF_CINV);
    float* sh_csq  = (float*)(smem + OFF_CSQ);
    float* sh_part = (float*)(smem + OFF_PART);

    // per-tile constants into smem
    if (tid < 128) {
        sh_einv[tid] = g_einv[row0 + tid];
        sh_esq[tid]  = g_esq[row0 + tid];
        sh_cinv[tid] = g_cinv[col0 + tid];
        sh_csq[tid]  = g_csq[col0 + tid];
    }

    // ---- stage loader: K-chunk kt into stage s ----
    const char* Ag0 = (const char*)(g_Abf + (size_t)row0 * D_DIM);
    const char* Bg0 = (const char*)(g_Cbf + (size_t)col0 * D_DIM);
    auto load_stage = [&](int kt, int s) {
        uint32_t abase = sb + OFF_STAGE + s * STAGE_BYTES;
        uint32_t bbase = abase + A_BYTES;
        const char* Ag = Ag0 + kt * 128;
        const char* Bg = Bg0 + kt * 128;
#pragma unroll
        for (int t = 0; t < 4; t++) {
            int ch = tid + t * 256;
            int r = ch >> 3, c = ch & 7;
            uint32_t bo = r * 128 + c * 16;
            cp_async16(abase + swz(bo), Ag + (size_t)r * 1024 + c * 16);
        }
#pragma unroll
        for (int t = 0; t < 4; t++) {
            int ch = tid + t * 256;
            int r = ch >> 3, c = ch & 7;
            uint32_t bo = r * 128 + c * 16;
            cp_async16(bbase + swz(bo), Bg + (size_t)r * 1024 + c * 16);
        }
        cp_commit();
    };

    load_stage(0, 0);
    load_stage(1, 1);

    float acc[4][4][4];
#pragma unroll
    for (int i = 0; i < 4; i++)
#pragma unroll
        for (int j = 0; j < 4; j++)
#pragma unroll
            for (int k = 0; k < 4; k++) acc[i][j][k] = 0.f;

    // per-thread ldmatrix addressing
    const int lrow = lane & 15;
    const int lc16 = lane >> 4;                       // 0/1 -> +16B
    const uint32_t aoff0 = (wy * 64 + lrow) * 128 + lc16 * 16;
    const uint32_t boff0 = (wx * 32 + lrow) * 128 + lc16 * 16;

#pragma unroll 1
    for (int kt = 0; kt < 8; kt++) {
        const int s = kt % STAGES;
        if (kt < 7) cp_wait<1>(); else cp_wait<0>();
        __syncthreads();

        uint32_t abase = sb + OFF_STAGE + s * STAGE_BYTES;
        uint32_t bbase = abase + A_BYTES;
#pragma unroll
        for (int kg = 0; kg < 4; kg++) {              // 4 x k16 steps
            uint32_t a[4][4], b[2][4];
#pragma unroll
            for (int mt = 0; mt < 4; mt++)
                ldmx4(a[mt], abase + swz(aoff0 + mt * 2048 + kg * 32));
#pragma unroll
            for (int nb = 0; nb < 2; nb++)
                ldmx4(b[nb], bbase + swz(boff0 + nb * 2048 + kg * 32));
#pragma unroll
            for (int mt = 0; mt < 4; mt++)
#pragma unroll
                for (int nt = 0; nt < 4; nt++)
                    mma16816(acc[mt][nt], a[mt], b[nt >> 1][nt & 1], b[nt >> 1][(nt & 1) + 2]);
        }

        if (kt + 2 < 8) load_stage(kt + 2, (kt + 2) % STAGES);
        else cp_commit();                              // keep group counts consistent
    }
    __syncthreads();

    // ---- fused softmax epilogue ----
    const float wv = *wp;
    const float bv = *bp;

    // cache this thread's 8 column constants
    float tcinv[8], tcsq[8];
    int   tcol[8];
#pragma unroll
    for (int nt = 0; nt < 4; nt++)
#pragma unroll
        for (int j = 0; j < 2; j++) {
            int cl = wx * 32 + nt * 8 + (lane & 3) * 2 + j;
            tcinv[nt * 2 + j] = sh_cinv[cl];
            tcsq[nt * 2 + j]  = sh_csq[cl];
            tcol[nt * 2 + j]  = col0 + cl;
        }

    float* part = sh_part + wx * 128;

#pragma unroll
    for (int mt = 0; mt < 4; mt++) {
#pragma unroll
        for (int half = 0; half < 2; half++) {
            int   rl   = wy * 64 + mt * 16 + (lane >> 2) + half * 8;
            int   r    = row0 + rl;
            float einv = sh_einv[rl];
            float esq  = sh_esq[rl];
            int   jown = r >> 5;

            float rsum = 0.f;
#pragma unroll
            for (int nt = 0; nt < 4; nt++) {
#pragma unroll
                for (int j = 0; j < 2; j++) {
                    float v = acc[mt][nt][half * 2 + j];
                    int   e = nt * 2 + j;
                    if (tcol[e] == jown) {
                        float dl   = fmaf(32.f, v, -esq) * (1.f / 31.f);
                        float clq  = (1024.f * tcsq[e] - 64.f * v + esq) * (1.f / 961.f);
                        float cosv = dl * einv * rsqrtf(clq);
                        float lg   = fmaxf(cosv, EPS) * wv + bv;
                        g_own[r]   = lg;
                        rsum += exp_fast(lg);
                    } else {
                        float lg = fmaxf(v * einv * tcinv[e], EPS) * wv + bv;
                        rsum += exp_fast(lg);
                    }
                }
            }
            // reduce across the 4 lanes sharing this row
            rsum += __shfl_xor_sync(0xffffffffu, rsum, 1);
            rsum += __shfl_xor_sync(0xffffffffu, rsum, 2);
            if ((lane & 3) == 0) part[rl] = rsum;
        }
    }
    __syncthreads();

    if (tid < 128) {
        g_Zp[(size_t)blockIdx.x * R_ROWS + row0 + tid] =
            sh_part[tid] + sh_part[128 + tid] + sh_part[256 + tid] + sh_part[384 + tid];
    }
}

// ---------------------------------------------------------------------------
// Kernel 4: final reduction  L = sum_r log(sum_p Zp) - own_logit
// ---------------------------------------------------------------------------
__global__ void loss_kernel(float* __restrict__ out) {
    const int tid = threadIdx.x;
    float s = 0.f;
    for (int r = tid; r < R_ROWS; r += 1024) {
        float z = 0.f;
#pragma unroll
        for (int p = 0; p < 8; p++) z += g_Zp[(size_t)p * R_ROWS + r];
        s += logf(z) - g_own[r];
    }
    __shared__ float sh[1024];
    sh[tid] = s;
    __syncthreads();
    for (int off = 512; off > 0; off >>= 1) {
        if (tid < off) sh[tid] += sh[tid + off];
        __syncthreads();
    }
    if (tid == 0) out[0] = sh[0];
}

// ---------------------------------------------------------------------------
extern "C" void kernel_launch(void* const* d_in, const int* in_sizes, int n_in,
                              void* d_out, int out_size) {
    const float* dvecs = (const float*)d_in[0];
    const float* w     = (const float*)d_in[1];
    const float* b     = (const float*)d_in[2];
    float* out         = (float*)d_out;

    static int attr_set = 0;
    if (!attr_set) {
        cudaFuncSetAttribute(gemm_loss_kernel,
                             cudaFuncAttributeMaxDynamicSharedMemorySize, SMEM_TOTAL);
        attr_set = 1;
    }

    conv_kernel<<<R_ROWS / 8, 256>>>(dvecs);
    centroid_kernel<<<N_SPK, 512>>>(dvecs);
    gemm_loss_kernel<<<dim3(8, 256), 256, SMEM_TOTAL>>>(w, b);
    loss_kernel<<<1, 1024>>>(out);
}

// round 4
// speedup vs baseline: 6.7314x; 1.1171x over previous
#include <cuda_runtime.h>
#include <cuda_bf16.h>
#include <math.h>
#include <stdint.h>

#define N_SPK 1024
#define M_UTT 32
#define D_DIM 512
#define R_ROWS (N_SPK * M_UTT)
#define EPS 1e-6f

// ---------------- device scratch (no allocations allowed) ----------------
__device__ __nv_bfloat16 g_Abf[R_ROWS * D_DIM];   // 32 MB  bf16 dvecs
__device__ __nv_bfloat16 g_Cbf[N_SPK * D_DIM];    // 1 MB   bf16 centroids
__device__ float g_csq[N_SPK];
__device__ float g_cinv[N_SPK];
__device__ float g_esq[R_ROWS];
__device__ float g_einv[R_ROWS];
__device__ float g_Zp[8 * R_ROWS];                // per-col-tile softmax partials
__device__ float g_own[R_ROWS];                   // own-speaker (LOO) logit
__device__ float g_bsum[128];                     // loss block partials

// ---------------- PTX helpers ----------------
__device__ __forceinline__ uint32_t smem_u32(const void* p) {
    uint32_t a;
    asm("{ .reg .u64 t; cvta.to.shared.u64 t, %1; cvt.u32.u64 %0, t; }" : "=r"(a) : "l"(p));
    return a;
}
__device__ __forceinline__ void cp_async16(uint32_t dst, const void* src) {
    asm volatile("cp.async.cg.shared.global.L2::128B [%0], [%1], 16;\n" :: "r"(dst), "l"(src));
}
__device__ __forceinline__ void cp_commit() {
    asm volatile("cp.async.commit_group;\n" ::: "memory");
}
template <int N>
__device__ __forceinline__ void cp_wait() {
    asm volatile("cp.async.wait_group %0;\n" :: "n"(N) : "memory");
}
__device__ __forceinline__ void ldmx4(uint32_t* r, uint32_t addr) {
    asm volatile("ldmatrix.sync.aligned.m8n8.x4.shared.b16 {%0,%1,%2,%3}, [%4];"
                 : "=r"(r[0]), "=r"(r[1]), "=r"(r[2]), "=r"(r[3]) : "r"(addr));
}
__device__ __forceinline__ void mma16816(float* c, const uint32_t* a, uint32_t b0, uint32_t b1) {
    asm volatile(
        "mma.sync.aligned.m16n8k16.row.col.f32.bf16.bf16.f32 "
        "{%0,%1,%2,%3}, {%4,%5,%6,%7}, {%8,%9}, {%0,%1,%2,%3};"
        : "+f"(c[0]), "+f"(c[1]), "+f"(c[2]), "+f"(c[3])
        : "r"(a[0]), "r"(a[1]), "r"(a[2]), "r"(a[3]), "r"(b0), "r"(b1));
}
__device__ __forceinline__ uint32_t swz(uint32_t bo) {   // SW128: bits[4:6] ^= bits[7:9]
    return bo ^ ((bo >> 3) & 0x70);
}

// fast exp on the FMA pipe (no MUFU): valid here for x in [-5, 5]
__device__ __forceinline__ float exp_fast(float x) {
    const float LOG2E = 1.4426950408889634f;
    float y = x * LOG2E;
    float z = y + 12582912.0f;                 // round-to-nearest via magic constant
    float f = y - (z - 12582912.0f);           // f in [-0.5, 0.5]
    int   n = __float_as_int(z) - 0x4B400000;
    float p = 0.001333355814642844f;
    p = fmaf(p, f, 0.009618129107628477f);
    p = fmaf(p, f, 0.055504108664821580f);
    p = fmaf(p, f, 0.240226506959100700f);
    p = fmaf(p, f, 0.693147180559945300f);
    p = fmaf(p, f, 1.0f);
    float s = __int_as_float((n + 127) << 23);
    return p * s;
}

// ---------------------------------------------------------------------------
// Kernel 1: fused prep. One block per speaker (256 thr, 8 warps x 4 rows).
//  - fp32->bf16 convert of the 32 rows
//  - per-row |e|^2, 1/|e|
//  - fp32 centroid (register partials -> smem reduce), bf16 C, |c|^2, 1/|c|
// ---------------------------------------------------------------------------
__global__ void __launch_bounds__(256) prep_kernel(const float* __restrict__ dvecs) {
    __shared__ float shc[8][512];      // per-warp centroid partials
    __shared__ float shr[256];         // csq reduction

    const int j    = blockIdx.x;
    const int tid  = threadIdx.x;
    const int wid  = tid >> 5;
    const int lane = tid & 31;

    const float2* base = (const float2*)(dvecs + (size_t)j * M_UTT * D_DIM);

    float2 csum[8];
#pragma unroll
    for (int k = 0; k < 8; k++) csum[k] = make_float2(0.f, 0.f);

#pragma unroll
    for (int r = 0; r < 4; r++) {
        const int m   = wid * 4 + r;
        const int row = j * M_UTT + m;
        const float2* src = base + (size_t)m * 256;
        __nv_bfloat162* dst = (__nv_bfloat162*)(g_Abf + (size_t)row * D_DIM);
        float s = 0.f;
#pragma unroll
        for (int k = 0; k < 8; k++) {
            float2 v = src[lane + k * 32];
            s += v.x * v.x + v.y * v.y;
            csum[k].x += v.x;
            csum[k].y += v.y;
            dst[lane + k * 32] = __floats2bfloat162_rn(v.x, v.y);
        }
#pragma unroll
        for (int off = 16; off > 0; off >>= 1) s += __shfl_xor_sync(0xffffffffu, s, off);
        if (lane == 0) {
            g_esq[row]  = s;
            g_einv[row] = rsqrtf(s);
        }
    }

    // dump per-warp centroid partials
    float2* myrow = (float2*)shc[wid];
#pragma unroll
    for (int k = 0; k < 8; k++) myrow[lane + k * 32] = csum[k];
    __syncthreads();

    // each thread owns one float2 column pair: sum 8 warp partials
    float2 tot = make_float2(0.f, 0.f);
#pragma unroll
    for (int w = 0; w < 8; w++) {
        float2 v = ((float2*)shc[w])[tid];
        tot.x += v.x;
        tot.y += v.y;
    }
    float cx = tot.x * (1.0f / M_UTT);
    float cy = tot.y * (1.0f / M_UTT);
    ((__nv_bfloat162*)(g_Cbf + (size_t)j * D_DIM))[tid] = __floats2bfloat162_rn(cx, cy);

    shr[tid] = cx * cx + cy * cy;
    __syncthreads();
    for (int off = 128; off > 0; off >>= 1) {
        if (tid < off) shr[tid] += shr[tid + off];
        __syncthreads();
    }
    if (tid == 0) {
        g_csq[j]  = shr[0];
        g_cinv[j] = rsqrtf(shr[0]);
    }
}

// ---------------------------------------------------------------------------
// Kernel 2: bf16 mma.sync GEMM (BM=128, BN=128, BK=64, 3-stage cp.async)
// + fused softmax epilogue.  Grid: (8 col tiles, 256 row tiles), 256 threads.
// ---------------------------------------------------------------------------
#define STAGES 3
#define A_BYTES 16384                  // 128 x 128B
#define B_BYTES 16384
#define STAGE_BYTES (A_BYTES + B_BYTES)
#define OFF_EINV  0
#define OFF_ESQ   512
#define OFF_CINV  1024
#define OFF_CSQ   1536
#define OFF_PART  2048                 // 4 x 128 floats
#define OFF_STAGE 4096
#define SMEM_TOTAL (OFF_STAGE + STAGES * STAGE_BYTES)   // 102400

__global__ void __launch_bounds__(256, 2)
gemm_loss_kernel(const float* __restrict__ wp, const float* __restrict__ bp) {
    extern __shared__ char smem[];
    const uint32_t sb = smem_u32(smem);
    const int tid  = threadIdx.x;
    const int wid  = tid >> 5;
    const int lane = tid & 31;
    const int wy   = wid >> 2;          // 0..1  (64-row slice)
    const int wx   = wid & 3;           // 0..3  (32-col slice)
    const int col0 = blockIdx.x * 128;
    const int row0 = blockIdx.y * 128;

    float* sh_einv = (float*)(smem + OFF_EINV);
    float* sh_esq  = (float*)(smem + OFF_ESQ);
    float* sh_cinv = (float*)(smem + OFF_CINV);
    float* sh_csq  = (float*)(smem + OFF_CSQ);
    float* sh_part = (float*)(smem + OFF_PART);

    if (tid < 128) {
        sh_einv[tid] = g_einv[row0 + tid];
        sh_esq[tid]  = g_esq[row0 + tid];
        sh_cinv[tid] = g_cinv[col0 + tid];
        sh_csq[tid]  = g_csq[col0 + tid];
    }

    const char* Ag0 = (const char*)(g_Abf + (size_t)row0 * D_DIM);
    const char* Bg0 = (const char*)(g_Cbf + (size_t)col0 * D_DIM);
    auto load_stage = [&](int kt, int s) {
        uint32_t abase = sb + OFF_STAGE + s * STAGE_BYTES;
        uint32_t bbase = abase + A_BYTES;
        const char* Ag = Ag0 + kt * 128;
        const char* Bg = Bg0 + kt * 128;
#pragma unroll
        for (int t = 0; t < 4; t++) {
            int ch = tid + t * 256;
            int r = ch >> 3, c = ch & 7;
            uint32_t bo = r * 128 + c * 16;
            cp_async16(abase + swz(bo), Ag + (size_t)r * 1024 + c * 16);
        }
#pragma unroll
        for (int t = 0; t < 4; t++) {
            int ch = tid + t * 256;
            int r = ch >> 3, c = ch & 7;
            uint32_t bo = r * 128 + c * 16;
            cp_async16(bbase + swz(bo), Bg + (size_t)r * 1024 + c * 16);
        }
        cp_commit();
    };

    load_stage(0, 0);
    load_stage(1, 1);

    float acc[4][4][4];
#pragma unroll
    for (int i = 0; i < 4; i++)
#pragma unroll
        for (int j = 0; j < 4; j++)
#pragma unroll
            for (int k = 0; k < 4; k++) acc[i][j][k] = 0.f;

    const int lrow = lane & 15;
    const int lc16 = lane >> 4;
    const uint32_t aoff0 = (wy * 64 + lrow) * 128 + lc16 * 16;
    const uint32_t boff0 = (wx * 32 + lrow) * 128 + lc16 * 16;

#pragma unroll 1
    for (int kt = 0; kt < 8; kt++) {
        const int s = kt % STAGES;
        if (kt < 7) cp_wait<1>(); else cp_wait<0>();
        __syncthreads();

        uint32_t abase = sb + OFF_STAGE + s * STAGE_BYTES;
        uint32_t bbase = abase + A_BYTES;
#pragma unroll
        for (int kg = 0; kg < 4; kg++) {
            uint32_t a[4][4], b[2][4];
#pragma unroll
            for (int mt = 0; mt < 4; mt++)
                ldmx4(a[mt], abase + swz(aoff0 + mt * 2048 + kg * 32));
#pragma unroll
            for (int nb = 0; nb < 2; nb++)
                ldmx4(b[nb], bbase + swz(boff0 + nb * 2048 + kg * 32));
#pragma unroll
            for (int mt = 0; mt < 4; mt++)
#pragma unroll
                for (int nt = 0; nt < 4; nt++)
                    mma16816(acc[mt][nt], a[mt], b[nt >> 1][nt & 1], b[nt >> 1][(nt & 1) + 2]);
        }

        if (kt + 2 < 8) load_stage(kt + 2, (kt + 2) % STAGES);
        else cp_commit();
    }
    __syncthreads();

    // ---- fused softmax epilogue ----
    const float wv = *wp;
    const float bv = *bp;

    float tcinv[8], tcsq[8];
    int   tcol[8];
#pragma unroll
    for (int nt = 0; nt < 4; nt++)
#pragma unroll
        for (int j = 0; j < 2; j++) {
            int cl = wx * 32 + nt * 8 + (lane & 3) * 2 + j;
            tcinv[nt * 2 + j] = sh_cinv[cl];
            tcsq[nt * 2 + j]  = sh_csq[cl];
            tcol[nt * 2 + j]  = col0 + cl;
        }

    float* part = sh_part + wx * 128;

#pragma unroll
    for (int mt = 0; mt < 4; mt++) {
#pragma unroll
        for (int half = 0; half < 2; half++) {
            int   rl   = wy * 64 + mt * 16 + (lane >> 2) + half * 8;
            int   r    = row0 + rl;
            float einv = sh_einv[rl];
            float esq  = sh_esq[rl];
            int   jown = r >> 5;

            float rsum = 0.f;
#pragma unroll
            for (int nt = 0; nt < 4; nt++) {
#pragma unroll
                for (int j = 0; j < 2; j++) {
                    float v = acc[mt][nt][half * 2 + j];
                    int   e = nt * 2 + j;
                    if (tcol[e] == jown) {
                        float dl   = fmaf(32.f, v, -esq) * (1.f / 31.f);
                        float clq  = (1024.f * tcsq[e] - 64.f * v + esq) * (1.f / 961.f);
                        float cosv = dl * einv * rsqrtf(clq);
                        float lg   = fmaxf(cosv, EPS) * wv + bv;
                        g_own[r]   = lg;
                        rsum += exp_fast(lg);
                    } else {
                        float lg = fmaxf(v * einv * tcinv[e], EPS) * wv + bv;
                        rsum += exp_fast(lg);
                    }
                }
            }
            rsum += __shfl_xor_sync(0xffffffffu, rsum, 1);
            rsum += __shfl_xor_sync(0xffffffffu, rsum, 2);
            if ((lane & 3) == 0) part[rl] = rsum;
        }
    }
    __syncthreads();

    if (tid < 128) {
        g_Zp[(size_t)blockIdx.x * R_ROWS + row0 + tid] =
            sh_part[tid] + sh_part[128 + tid] + sh_part[256 + tid] + sh_part[384 + tid];
    }
}

// ---------------------------------------------------------------------------
// Kernel 3: parallel loss partials. 128 blocks x 256 threads, 1 row/thread.
// ---------------------------------------------------------------------------
__global__ void __launch_bounds__(256) loss_part_kernel() {
    const int tid = threadIdx.x;
    const int r   = blockIdx.x * 256 + tid;
    float z = 0.f;
#pragma unroll
    for (int p = 0; p < 8; p++) z += g_Zp[(size_t)p * R_ROWS + r];
    float s = logf(z) - g_own[r];

    __shared__ float sh[256];
    sh[tid] = s;
    __syncthreads();
    for (int off = 128; off > 0; off >>= 1) {
        if (tid < off) sh[tid] += sh[tid + off];
        __syncthreads();
    }
    if (tid == 0) g_bsum[blockIdx.x] = sh[0];
}

// ---------------------------------------------------------------------------
// Kernel 4: final 128-way sum.
// ---------------------------------------------------------------------------
__global__ void loss_final_kernel(float* __restrict__ out) {
    const int tid = threadIdx.x;            // 128 threads
    float s = g_bsum[tid];
#pragma unroll
    for (int off = 16; off > 0; off >>= 1) s += __shfl_xor_sync(0xffffffffu, s, off);
    __shared__ float sh[4];
    if ((tid & 31) == 0) sh[tid >> 5] = s;
    __syncthreads();
    if (tid == 0) out[0] = sh[0] + sh[1] + sh[2] + sh[3];
}

// ---------------------------------------------------------------------------
extern "C" void kernel_launch(void* const* d_in, const int* in_sizes, int n_in,
                              void* d_out, int out_size) {
    const float* dvecs = (const float*)d_in[0];
    const float* w     = (const float*)d_in[1];
    const float* b     = (const float*)d_in[2];
    float* out         = (float*)d_out;

    cudaFuncSetAttribute(gemm_loss_kernel,
                         cudaFuncAttributeMaxDynamicSharedMemorySize, SMEM_TOTAL);

    prep_kernel<<<N_SPK, 256>>>(dvecs);
    gemm_loss_kernel<<<dim3(8, 256), 256, SMEM_TOTAL>>>(w, b);
    loss_part_kernel<<<128, 256>>>();
    loss_final_kernel<<<1, 128>>>(out);
}